// round 17
// baseline (speedup 1.0000x reference)
#include <cuda_runtime.h>

#define BATCH 2048
#define TT    2048
#define HH    25

typedef unsigned long long u64;

// Packed f32x2 ops (Blackwell, PTX-only): two fp32 ops per instruction.
__device__ __forceinline__ u64 ffma2(u64 a, u64 b, u64 c) {
    u64 d; asm("fma.rn.f32x2 %0, %1, %2, %3;" : "=l"(d) : "l"(a), "l"(b), "l"(c)); return d;
}
__device__ __forceinline__ u64 fmul2(u64 a, u64 b) {
    u64 d; asm("mul.rn.f32x2 %0, %1, %2;" : "=l"(d) : "l"(a), "l"(b)); return d;
}
__device__ __forceinline__ u64 fadd2(u64 a, u64 b) {
    u64 d; asm("add.rn.f32x2 %0, %1, %2;" : "=l"(d) : "l"(a), "l"(b)); return d;
}
__device__ __forceinline__ u64 pk2(float lo, float hi) {
    u64 r; asm("mov.b64 %0, {%1, %2};" : "=l"(r) : "f"(lo), "f"(hi)); return r;
}
__device__ __forceinline__ float lo2(u64 a) { return __uint_as_float((unsigned)a); }
__device__ __forceinline__ float hi2(u64 a) { return __uint_as_float((unsigned)(a >> 32)); }

// MUFU.TANH: single-instruction tanh.
__device__ __forceinline__ float tanha(float x) {
    float r; asm("tanh.approx.f32 %0, %1;" : "=f"(r) : "f"(x)); return r;
}

__device__ __forceinline__ u64 lds64(unsigned a) {
    u64 r; asm volatile("ld.shared.b64 %0, [%1];" : "=l"(r) : "r"(a) : "memory"); return r;
}
__device__ __forceinline__ void lds128(unsigned a, u64& p0, u64& p1) {
    asm volatile("ld.shared.v2.u64 {%0, %1}, [%2];" : "=l"(p0), "=l"(p1) : "r"(a) : "memory");
}
__device__ __forceinline__ void sts32(unsigned a, float v) {
    asm volatile("st.shared.f32 [%0], %1;" :: "r"(a), "f"(v) : "memory");
}

// ONE sequence per warp, unit-owned, MUFU.TANH, split dot chains, lane-25
// dense head. Same step body as R16 but halved per warp: 2048 CTAs of 32
// threads -> 13.8 warps/SM (3.46 warps/SMSP, 2x the stall-hiding streams of
// the 2-seq layout) at the SAME total FMA work. launch_bounds(32,14) caps
// regs at 146 (estimate ~140 live: 104 weight regs + load window + split
// accumulators + state) -- deliberately tight, no spill expected.
// Lane j<25 owns unit j: gate rows i,f,g,o in slots 0..3 (i,f,o prescaled by
// 0.5 for sigmoid(z)=0.5+0.5*tanh(z/2); g by 1.0); c_j, h_j lane-local.
// Lane 25 slot 0 = unscaled dense row (bias in pair-12 hi slot against the
// const-1.0 in h slot 25): its raw dot over h[t-1] IS y[t-1], stored direct.
// Dots split into halves (pairs 0-6 / 7-12) + one packed add. Per step:
// 6 LDS.128 + 1 LDS.64 + 1 STS.32. Warp-private smem, in-order per-warp LSU
// -> no syncwarp in the loop (validated R10/R13/R14/R16).
__global__ void __launch_bounds__(32, 14)
lstm_1s(const float* __restrict__ x,        // [B, T, 1]
        const float* __restrict__ w_ih,     // [4H, 1]
        const float* __restrict__ w_hh,     // [4H, H]
        const float* __restrict__ b_ih,     // [4H]
        const float* __restrict__ b_hh,     // [4H]
        const float* __restrict__ w_dense,  // [1, H]
        const float* __restrict__ b_dense,  // [1]
        float* __restrict__ out)            // [B, T, 1]
{
    __shared__ __align__(16) float hsh[2][32];   // [ping][slot]

    const int lane = (int)(threadIdx.x & 31u);
    const int seq  = blockIdx.x;

    // ---- per-lane weights: slots 0..3 ----
    u64 W[4][13];
    float uu[4];
    if (lane < HH) {
        const int j = lane;
#pragma unroll
        for (int g = 0; g < 4; g++) {
            const float sc = (g == 2) ? 1.0f : 0.5f;
            const float* row = w_hh + (g * HH + j) * HH;
#pragma unroll
            for (int p = 0; p < 12; p++)
                W[g][p] = pk2(sc * row[2 * p], sc * row[2 * p + 1]);
            W[g][12] = pk2(sc * row[24],
                           sc * (b_ih[g * HH + j] + b_hh[g * HH + j]));
            uu[g] = sc * w_ih[g * HH + j];
        }
    } else if (lane == HH) {      // lane 25: slot 0 = dense row (unscaled)
#pragma unroll
        for (int p = 0; p < 12; p++)
            W[0][p] = pk2(w_dense[2 * p], w_dense[2 * p + 1]);
        W[0][12] = pk2(w_dense[24], b_dense[0]);
#pragma unroll
        for (int g = 1; g < 4; g++)
#pragma unroll
            for (int p = 0; p < 13; p++) W[g][p] = 0ull;
        uu[0] = uu[1] = uu[2] = uu[3] = 0.0f;
    } else {                      // lanes 26..31: inert
#pragma unroll
        for (int g = 0; g < 4; g++)
#pragma unroll
            for (int p = 0; p < 13; p++) W[g][p] = 0ull;
        uu[0] = uu[1] = uu[2] = uu[3] = 0.0f;
    }

    const float2* xp = reinterpret_cast<const float2*>(x + (size_t)seq * TT);
    float* orow = out + (size_t)seq * TT;

    const unsigned base = (unsigned)__cvta_generic_to_shared(&hsh[0][0]);
    const unsigned h0 = base, h1 = base + 128u;
    const unsigned shl = 4u * (unsigned)lane;

    // init: h = 0, slot 25 = 1.0 (permanent bias feed; lane 25 never stores)
    {
        const float v = (lane == HH) ? 1.0f : 0.0f;
        hsh[0][lane] = v;
        hsh[1][lane] = v;
    }
    __syncwarp();

    float c = 0.0f;
    float2 xq = xp[0];

    // One LSTM step. RA: read buf (h[t-1] pairs + const-1 slot); WA: write
    // buf; XV: x[t]; stores y[t-1] (dense dot on h[t-1]) when STORE0.
#define STEP(RA, WA, XV, STORE0, GT)                                          \
    {                                                                         \
        u64 p0, p1, p2, p3, p4, p5, p6, p7, p8, p9, p10, p11, p12;            \
        lds128((RA) +  0u, p0, p1);                                           \
        lds128((RA) + 16u, p2, p3);                                           \
        lds128((RA) + 32u, p4, p5);                                           \
        lds128((RA) + 48u, p6, p7);                                           \
        lds128((RA) + 64u, p8, p9);                                           \
        lds128((RA) + 80u, p10, p11);                                         \
        p12 = lds64((RA) + 96u);                                              \
        u64 L0 = fmul2(p0, W[0][0]), L1 = fmul2(p0, W[1][0]);                 \
        u64 L2 = fmul2(p0, W[2][0]), L3 = fmul2(p0, W[3][0]);                 \
        u64 H0 = fmul2(p7, W[0][7]), H1 = fmul2(p7, W[1][7]);                 \
        u64 H2 = fmul2(p7, W[2][7]), H3 = fmul2(p7, W[3][7]);                 \
        L0 = ffma2(p1, W[0][1], L0);  L1 = ffma2(p1, W[1][1], L1);            \
        L2 = ffma2(p1, W[2][1], L2);  L3 = ffma2(p1, W[3][1], L3);            \
        H0 = ffma2(p8, W[0][8], H0);  H1 = ffma2(p8, W[1][8], H1);            \
        H2 = ffma2(p8, W[2][8], H2);  H3 = ffma2(p8, W[3][8], H3);            \
        L0 = ffma2(p2, W[0][2], L0);  L1 = ffma2(p2, W[1][2], L1);            \
        L2 = ffma2(p2, W[2][2], L2);  L3 = ffma2(p2, W[3][2], L3);            \
        H0 = ffma2(p9, W[0][9], H0);  H1 = ffma2(p9, W[1][9], H1);            \
        H2 = ffma2(p9, W[2][9], H2);  H3 = ffma2(p9, W[3][9], H3);            \
        L0 = ffma2(p3, W[0][3], L0);  L1 = ffma2(p3, W[1][3], L1);            \
        L2 = ffma2(p3, W[2][3], L2);  L3 = ffma2(p3, W[3][3], L3);            \
        H0 = ffma2(p10, W[0][10], H0); H1 = ffma2(p10, W[1][10], H1);         \
        H2 = ffma2(p10, W[2][10], H2); H3 = ffma2(p10, W[3][10], H3);         \
        L0 = ffma2(p4, W[0][4], L0);  L1 = ffma2(p4, W[1][4], L1);            \
        L2 = ffma2(p4, W[2][4], L2);  L3 = ffma2(p4, W[3][4], L3);            \
        H0 = ffma2(p11, W[0][11], H0); H1 = ffma2(p11, W[1][11], H1);         \
        H2 = ffma2(p11, W[2][11], H2); H3 = ffma2(p11, W[3][11], H3);         \
        L0 = ffma2(p5, W[0][5], L0);  L1 = ffma2(p5, W[1][5], L1);            \
        L2 = ffma2(p5, W[2][5], L2);  L3 = ffma2(p5, W[3][5], L3);            \
        H0 = ffma2(p12, W[0][12], H0); H1 = ffma2(p12, W[1][12], H1);         \
        H2 = ffma2(p12, W[2][12], H2); H3 = ffma2(p12, W[3][12], H3);         \
        L0 = ffma2(p6, W[0][6], L0);  L1 = ffma2(p6, W[1][6], L1);            \
        L2 = ffma2(p6, W[2][6], L2);  L3 = ffma2(p6, W[3][6], L3);            \
        const u64 S0 = fadd2(L0, H0), S1 = fadd2(L1, H1);                     \
        const u64 S2 = fadd2(L2, H2), S3 = fadd2(L3, H3);                     \
        const float a0 = fmaf((XV), uu[0], lo2(S0) + hi2(S0));                \
        const float a1 = fmaf((XV), uu[1], lo2(S1) + hi2(S1));                \
        const float a2 = fmaf((XV), uu[2], lo2(S2) + hi2(S2));                \
        const float a3 = fmaf((XV), uu[3], lo2(S3) + hi2(S3));                \
        /* lane 25 slot 0: raw dense dot on h[t-1] == y[t-1] (uu=0) */        \
        if ((STORE0) && lane == HH) orow[(GT) - 1] = a0;                      \
        const float t0 = tanha(a0), t1 = tanha(a1);                           \
        const float t2 = tanha(a2), t3 = tanha(a3);                           \
        const float gi = fmaf(0.5f, t0, 0.5f);                                \
        const float gf = fmaf(0.5f, t1, 0.5f);                                \
        const float go = fmaf(0.5f, t3, 0.5f);                                \
        c = fmaf(gf, c, gi * t2);                                             \
        const float hv = go * tanha(c);                                       \
        if (lane < HH) sts32((WA) + shl, hv);                                 \
    }

#pragma unroll 1
    for (int tb = 0; tb < TT / 2; tb++) {
        const int tn = (tb + 1 < TT / 2) ? tb + 1 : tb;
        float2 xn = xp[tn];
        STEP(h0, h1, xq.x, (tb > 0), 2 * tb)
        STEP(h1, h0, xq.y, true,     2 * tb + 1)
        xq = xn;
    }
#undef STEP

    // tail: y[T-1] from final h (ping 0) via lane 25's dense chain (slot 0)
    __syncwarp();
    {
        u64 d = fmul2(lds64(h0), W[0][0]);
#pragma unroll
        for (int p = 1; p < 13; p++)
            d = ffma2(lds64(h0 + 8u * p), W[0][p], d);
        if (lane == HH) orow[TT - 1] = lo2(d) + hi2(d);
    }
}

extern "C" void kernel_launch(void* const* d_in, const int* in_sizes, int n_in,
                              void* d_out, int out_size) {
    const float* x       = (const float*)d_in[0];
    const float* w_ih    = (const float*)d_in[1];
    const float* w_hh    = (const float*)d_in[2];
    const float* b_ih    = (const float*)d_in[3];
    const float* b_hh    = (const float*)d_in[4];
    const float* w_dense = (const float*)d_in[5];
    const float* b_dense = (const float*)d_in[6];
    float* out = (float*)d_out;

    // 2048 CTAs x 32 threads: one warp per CTA, ONE sequence per warp.
    // 14 CTAs/SM (reg cap 146) -> 13.8 warps/SM, single wave, 2x the
    // stall-hiding streams per SMSP at the same total FMA work.
    lstm_1s<<<BATCH, 32>>>(x, w_ih, w_hh, b_ih, b_hh,
                           w_dense, b_dense, out);
}